// round 15
// baseline (speedup 1.0000x reference)
#include <cuda_runtime.h>
#include <cuda_bf16.h>

// x:    (b=8, t=50, f=129, c1=32, c2=32) float32
// mask: (g=8, f=129) float32
// out:  (b=8, t=50, g=8, c1=32, c2=32) float32
//
// out[b,t,g,:,:] = sum_{f in band g} x[b,t,f,:,:] / count[g]
//
// DRAM-BW-bound (~222.8 MB irreducible, ~6 TB/s sustained). Champion layout:
// one CTA per (b,t, band-pair), grid 1600, shared ballot preamble, MLP-8,
// lb(256,4). This round: SELECT-FREE dual-band interleave — two fixed
// pointers + two fixed accumulator sets, 4+4 loads per iteration over
// min(c0,c1), then an MLP-8 tail on the longer band. Removes the mid-CTA
// drain/restart bubble without R8's per-load predicate overhead.

#define N_F      129
#define N_BANDS  8
#define PIX4     256        // 32*32 pixels / 4 floats

__global__ __launch_bounds__(256, 4) void band_avg_kernel(
    const float* __restrict__ x,
    const float* __restrict__ masks,
    float* __restrict__ out)
{
    __shared__ unsigned bits[2][5];        // ballot bitmap per band
    __shared__ int   s_start[2], s_cnt[2], s_contig[2];
    __shared__ float s_inv[2];

    const int tid = threadIdx.x;
    const int bid = blockIdx.x;            // 0..1599
    const int gp  = bid & 3;               // pair id 0..3
    const int bt  = bid >> 2;              // (b,t) tile 0..399
    const int g0  = gp;
    const int g1  = (N_BANDS - 1) - gp;

    // --- parallel mask compaction for both bands (warps 0..4) ---
    const int wid = tid >> 5;
    if (wid < 5) {
        bool on0 = false, on1 = false;
        if (tid < N_F) {
            on0 = (masks[g0 * N_F + tid] > 0.5f);
            on1 = (masks[g1 * N_F + tid] > 0.5f);
        }
        unsigned b0 = __ballot_sync(0xffffffffu, on0);
        unsigned b1 = __ballot_sync(0xffffffffu, on1);
        if ((tid & 31) == 0) { bits[0][wid] = b0; bits[1][wid] = b1; }
    }
    __syncthreads();

    if (tid < 2) {
        int total = 0, first = -1, last = -1;
        #pragma unroll
        for (int w = 0; w < 5; ++w) {
            unsigned b = bits[tid][w];
            total += __popc(b);
            if (b) {
                if (first < 0) first = w * 32 + __ffs(b) - 1;
                last = w * 32 + 31 - __clz(b);
            }
        }
        s_start[tid]  = first;
        s_cnt[tid]    = total;
        s_contig[tid] = (last - first + 1 == total) ? 1 : 0;
        s_inv[tid]    = 1.0f / (float)total;
    }
    __syncthreads();

    const float4* __restrict__ xin =
        reinterpret_cast<const float4*>(x) + ((size_t)bt * (N_F * PIX4) + tid);
    float4* __restrict__ o4 =
        reinterpret_cast<float4*>(out) + ((size_t)bt * (N_BANDS * PIX4) + tid);

    if (s_contig[0] && s_contig[1]) {
        const int c0 = s_cnt[0];
        const int c1 = s_cnt[1];
        const int cm = (c0 < c1) ? c0 : c1;

        const float4* __restrict__ p0 = xin + (size_t)s_start[0] * PIX4;
        const float4* __restrict__ p1 = xin + (size_t)s_start[1] * PIX4;

        float a0x = 0.f, a0y = 0.f, a0z = 0.f, a0w = 0.f;   // band 0
        float a1x = 0.f, a1y = 0.f, a1z = 0.f, a1w = 0.f;   // band 1

        // --- interleaved phase: 4+4 independent loads per iteration ---
        int k = 0;
        #pragma unroll 1
        for (; k + 4 <= cm; k += 4) {
            float4 u0 = __ldcs(&p0[(size_t)(k + 0) * PIX4]);
            float4 u1 = __ldcs(&p0[(size_t)(k + 1) * PIX4]);
            float4 u2 = __ldcs(&p0[(size_t)(k + 2) * PIX4]);
            float4 u3 = __ldcs(&p0[(size_t)(k + 3) * PIX4]);
            float4 w0 = __ldcs(&p1[(size_t)(k + 0) * PIX4]);
            float4 w1 = __ldcs(&p1[(size_t)(k + 1) * PIX4]);
            float4 w2 = __ldcs(&p1[(size_t)(k + 2) * PIX4]);
            float4 w3 = __ldcs(&p1[(size_t)(k + 3) * PIX4]);
            a0x += u0.x; a0y += u0.y; a0z += u0.z; a0w += u0.w;
            a1x += w0.x; a1y += w0.y; a1z += w0.z; a1w += w0.w;
            a0x += u1.x; a0y += u1.y; a0z += u1.z; a0w += u1.w;
            a1x += w1.x; a1y += w1.y; a1z += w1.z; a1w += w1.w;
            a0x += u2.x; a0y += u2.y; a0z += u2.z; a0w += u2.w;
            a1x += w2.x; a1y += w2.y; a1z += w2.z; a1w += w2.w;
            a0x += u3.x; a0y += u3.y; a0z += u3.z; a0w += u3.w;
            a1x += w3.x; a1y += w3.y; a1z += w3.z; a1w += w3.w;
        }
        // finish the shared prefix (scalar)
        #pragma unroll 1
        for (; k < cm; ++k) {
            float4 u = __ldcs(&p0[(size_t)k * PIX4]);
            float4 w = __ldcs(&p1[(size_t)k * PIX4]);
            a0x += u.x; a0y += u.y; a0z += u.z; a0w += u.w;
            a1x += w.x; a1y += w.y; a1z += w.z; a1w += w.w;
        }

        // --- tail: the longer band continues with MLP-8 ---
        {
            const bool band1_longer = (c1 > c0);
            const float4* __restrict__ pt = band1_longer ? p1 : p0;
            const int ct = band1_longer ? c1 : c0;
            float tx = 0.f, ty = 0.f, tz = 0.f, tw = 0.f;
            float sx = 0.f, sy = 0.f, sz = 0.f, sw = 0.f;
            int j = cm;
            #pragma unroll 1
            for (; j + 8 <= ct; j += 8) {
                float4 v0 = __ldcs(&pt[(size_t)(j + 0) * PIX4]);
                float4 v1 = __ldcs(&pt[(size_t)(j + 1) * PIX4]);
                float4 v2 = __ldcs(&pt[(size_t)(j + 2) * PIX4]);
                float4 v3 = __ldcs(&pt[(size_t)(j + 3) * PIX4]);
                float4 v4 = __ldcs(&pt[(size_t)(j + 4) * PIX4]);
                float4 v5 = __ldcs(&pt[(size_t)(j + 5) * PIX4]);
                float4 v6 = __ldcs(&pt[(size_t)(j + 6) * PIX4]);
                float4 v7 = __ldcs(&pt[(size_t)(j + 7) * PIX4]);
                tx += v0.x; ty += v0.y; tz += v0.z; tw += v0.w;
                sx += v1.x; sy += v1.y; sz += v1.z; sw += v1.w;
                tx += v2.x; ty += v2.y; tz += v2.z; tw += v2.w;
                sx += v3.x; sy += v3.y; sz += v3.z; sw += v3.w;
                tx += v4.x; ty += v4.y; tz += v4.z; tw += v4.w;
                sx += v5.x; sy += v5.y; sz += v5.z; sw += v5.w;
                tx += v6.x; ty += v6.y; tz += v6.z; tw += v6.w;
                sx += v7.x; sy += v7.y; sz += v7.z; sw += v7.w;
            }
            #pragma unroll 4
            for (; j < ct; ++j) {
                float4 v = __ldcs(&pt[(size_t)j * PIX4]);
                tx += v.x; ty += v.y; tz += v.z; tw += v.w;
            }
            tx += sx; ty += sy; tz += sz; tw += sw;
            if (band1_longer) { a1x += tx; a1y += ty; a1z += tz; a1w += tw; }
            else              { a0x += tx; a0y += ty; a0z += tz; a0w += tw; }
        }

        const float i0 = s_inv[0], i1 = s_inv[1];
        float4 r0, r1;
        r0.x = a0x * i0; r0.y = a0y * i0; r0.z = a0z * i0; r0.w = a0w * i0;
        r1.x = a1x * i1; r1.y = a1y * i1; r1.z = a1z * i1; r1.w = a1w * i1;
        o4[(size_t)g0 * PIX4] = r0;
        o4[(size_t)g1 * PIX4] = r1;
    } else {
        // generic fallback: iterate the bitmaps (unused for reference mask)
        #pragma unroll 1
        for (int s = 0; s < 2; ++s) {
            const int g = s ? g1 : g0;
            float ax = 0.f, ay = 0.f, az = 0.f, aw = 0.f;
            #pragma unroll 1
            for (int f = 0; f < N_F; ++f) {
                if ((bits[s][f >> 5] >> (f & 31)) & 1u) {
                    float4 v = __ldcs(&xin[(size_t)f * PIX4]);
                    ax += v.x; ay += v.y; az += v.z; aw += v.w;
                }
            }
            const float inv = s_inv[s];
            float4 r;
            r.x = ax * inv; r.y = ay * inv; r.z = az * inv; r.w = aw * inv;
            o4[(size_t)g * PIX4] = r;
        }
    }
}

extern "C" void kernel_launch(void* const* d_in, const int* in_sizes, int n_in,
                              void* d_out, int out_size)
{
    const float* x     = (const float*)d_in[0];
    const float* masks = (const float*)d_in[1];
    if (n_in >= 2 && in_sizes[0] < in_sizes[1]) {
        x     = (const float*)d_in[1];
        masks = (const float*)d_in[0];
    }
    float* out = (float*)d_out;

    const int n_blocks = 8 * 50 * (N_BANDS / 2);  // 1600: one per (b,t,pair)
    band_avg_kernel<<<n_blocks, 256>>>(x, masks, out);
}

// round 16
// speedup vs baseline: 1.0172x; 1.0172x over previous
#include <cuda_runtime.h>
#include <cuda_bf16.h>

// x:    (b=8, t=50, f=129, c1=32, c2=32) float32
// mask: (g=8, f=129) float32
// out:  (b=8, t=50, g=8, c1=32, c2=32) float32
//
// out[b,t,g,:,:] = sum_{f in band g} x[b,t,f,:,:] / count[g]
//
// FINAL CHAMPION (R7/R12 config). DRAM-BW-bound: 222.8 MB irreducible
// traffic at the measured ~6.0 TB/s sustained HBM rate -> ~36.5 us kernel
// floor. 15 rounds of single-variable sweeps (CTA decomposition, occupancy,
// MLP depth, band fusion/interleave, preamble style, L2 load/store policies,
// launch order) all tie or regress vs this config. Design: one CTA per
// (b,t, band-pair), grid 1600, shared-memory ballot preamble, two sequential
// contiguous band loops with 8 independent float4 __ldcs loads in flight per
// thread, launch_bounds(256,4).

#define N_F      129
#define N_BANDS  8
#define PIX4     256        // 32*32 pixels / 4 floats

__global__ __launch_bounds__(256, 4) void band_avg_kernel(
    const float* __restrict__ x,
    const float* __restrict__ masks,
    float* __restrict__ out)
{
    __shared__ unsigned bits[2][5];        // ballot bitmap per band
    __shared__ int   s_start[2], s_cnt[2], s_contig[2];
    __shared__ float s_inv[2];

    const int tid = threadIdx.x;
    const int bid = blockIdx.x;            // 0..1599
    const int gp  = bid & 3;               // pair id 0..3
    const int bt  = bid >> 2;              // (b,t) tile 0..399
    const int g0  = gp;
    const int g1  = (N_BANDS - 1) - gp;

    // --- parallel mask compaction for both bands (warps 0..4) ---
    const int wid = tid >> 5;
    if (wid < 5) {
        bool on0 = false, on1 = false;
        if (tid < N_F) {
            on0 = (masks[g0 * N_F + tid] > 0.5f);
            on1 = (masks[g1 * N_F + tid] > 0.5f);
        }
        unsigned b0 = __ballot_sync(0xffffffffu, on0);
        unsigned b1 = __ballot_sync(0xffffffffu, on1);
        if ((tid & 31) == 0) { bits[0][wid] = b0; bits[1][wid] = b1; }
    }
    __syncthreads();

    if (tid < 2) {
        int total = 0, first = -1, last = -1;
        #pragma unroll
        for (int w = 0; w < 5; ++w) {
            unsigned b = bits[tid][w];
            total += __popc(b);
            if (b) {
                if (first < 0) first = w * 32 + __ffs(b) - 1;
                last = w * 32 + 31 - __clz(b);
            }
        }
        s_start[tid]  = first;
        s_cnt[tid]    = total;
        s_contig[tid] = (last - first + 1 == total) ? 1 : 0;
        s_inv[tid]    = 1.0f / (float)total;
    }
    __syncthreads();

    const float4* __restrict__ xin =
        reinterpret_cast<const float4*>(x) + ((size_t)bt * (N_F * PIX4) + tid);
    float4* __restrict__ o4 =
        reinterpret_cast<float4*>(out) + ((size_t)bt * (N_BANDS * PIX4) + tid);

    #pragma unroll 1
    for (int s = 0; s < 2; ++s) {
        const int   g     = s ? g1 : g0;
        const int   start = s_start[s];
        const int   c     = s_cnt[s];
        const float inv   = s_inv[s];

        float ax = 0.0f, ay = 0.0f, az = 0.0f, aw = 0.0f;
        float bx = 0.0f, by = 0.0f, bz = 0.0f, bw = 0.0f;

        if (s_contig[s]) {
            const float4* __restrict__ p = xin + (size_t)start * PIX4;
            // main loop: 8 independent loads in flight per thread
            int k = 0;
            #pragma unroll 1
            for (; k + 8 <= c; k += 8) {
                float4 v0 = __ldcs(&p[(size_t)(k + 0) * PIX4]);
                float4 v1 = __ldcs(&p[(size_t)(k + 1) * PIX4]);
                float4 v2 = __ldcs(&p[(size_t)(k + 2) * PIX4]);
                float4 v3 = __ldcs(&p[(size_t)(k + 3) * PIX4]);
                float4 v4 = __ldcs(&p[(size_t)(k + 4) * PIX4]);
                float4 v5 = __ldcs(&p[(size_t)(k + 5) * PIX4]);
                float4 v6 = __ldcs(&p[(size_t)(k + 6) * PIX4]);
                float4 v7 = __ldcs(&p[(size_t)(k + 7) * PIX4]);
                ax += v0.x; ay += v0.y; az += v0.z; aw += v0.w;
                bx += v1.x; by += v1.y; bz += v1.z; bw += v1.w;
                ax += v2.x; ay += v2.y; az += v2.z; aw += v2.w;
                bx += v3.x; by += v3.y; bz += v3.z; bw += v3.w;
                ax += v4.x; ay += v4.y; az += v4.z; aw += v4.w;
                bx += v5.x; by += v5.y; bz += v5.z; bw += v5.w;
                ax += v6.x; ay += v6.y; az += v6.z; aw += v6.w;
                bx += v7.x; by += v7.y; bz += v7.z; bw += v7.w;
            }
            #pragma unroll 4
            for (; k < c; ++k) {
                float4 v = __ldcs(&p[(size_t)k * PIX4]);
                ax += v.x; ay += v.y; az += v.z; aw += v.w;
            }
        } else {
            // generic fallback: iterate the bitmap (unused for reference mask)
            #pragma unroll 1
            for (int f = 0; f < N_F; ++f) {
                if ((bits[s][f >> 5] >> (f & 31)) & 1u) {
                    float4 v = __ldcs(&xin[(size_t)f * PIX4]);
                    ax += v.x; ay += v.y; az += v.z; aw += v.w;
                }
            }
        }

        float4 r;
        r.x = (ax + bx) * inv;
        r.y = (ay + by) * inv;
        r.z = (az + bz) * inv;
        r.w = (aw + bw) * inv;
        o4[(size_t)g * PIX4] = r;
    }
}

extern "C" void kernel_launch(void* const* d_in, const int* in_sizes, int n_in,
                              void* d_out, int out_size)
{
    const float* x     = (const float*)d_in[0];
    const float* masks = (const float*)d_in[1];
    if (n_in >= 2 && in_sizes[0] < in_sizes[1]) {
        x     = (const float*)d_in[1];
        masks = (const float*)d_in[0];
    }
    float* out = (float*)d_out;

    const int n_blocks = 8 * 50 * (N_BANDS / 2);  // 1600: one per (b,t,pair)
    band_avg_kernel<<<n_blocks, 256>>>(x, masks, out);
}